// round 16
// baseline (speedup 1.0000x reference)
#include <cuda_runtime.h>
#include <cuda_bf16.h>
#include <cuda_fp16.h>
#include <cstdint>

#define N_NODES 100000
#define N_EDGES 1600000
#define D 128
#define BCAP 64          // bucket capacity; P(deg>=64)~1e-20 for Poisson(16)

// Scratch (static __device__ per allocation rules)
__device__ __half g_x16[N_NODES * D];                   // fp16 (ego+side) for GEMM
__device__ __half g_ego16[N_NODES * D];                 // fp16 mirror of ego
__device__ int    g_cnt[N_NODES];                       // per-dst cursor/degree
__device__ unsigned long long g_buckets[(size_t)N_NODES * BCAP];
__device__ int    g_is64;

__device__ __forceinline__ uint32_t h2_bits(__half2 h) {
    return *reinterpret_cast<uint32_t*>(&h);
}
__device__ __forceinline__ __half2 bits_h2(uint32_t u) {
    return *reinterpret_cast<__half2*>(&u);
}

// ---------------------------------------------------------------------------
// 0) prep: fused detect + zero-cursors + fp16 convert (one launch).
// ---------------------------------------------------------------------------
__global__ void prep_kernel(const float* __restrict__ ego,
                            const long long* __restrict__ ei) {
    int i = blockIdx.x * blockDim.x + threadIdx.x;

    if (blockIdx.x == 0 && threadIdx.x < 32) {
        long long v = ei[threadIdx.x];
        unsigned bad = __ballot_sync(0xffffffffu,
                                     (unsigned long long)v >= (unsigned long long)N_NODES);
        if (threadIdx.x == 0) g_is64 = (bad == 0u);
    }

    if (i < N_NODES) g_cnt[i] = 0;

    const int n8 = N_NODES * D / 8;
    if (i < n8) {
        float4 a = reinterpret_cast<const float4*>(ego)[2 * i];
        float4 b = reinterpret_cast<const float4*>(ego)[2 * i + 1];
        uint4 o;
        o.x = h2_bits(__floats2half2_rn(a.x, a.y));
        o.y = h2_bits(__floats2half2_rn(a.z, a.w));
        o.z = h2_bits(__floats2half2_rn(b.x, b.y));
        o.w = h2_bits(__floats2half2_rn(b.z, b.w));
        reinterpret_cast<uint4*>(g_ego16)[i] = o;
    }
}

// ---------------------------------------------------------------------------
// 1) fill: direct bucketing (measured-best scalar form; ~L2-sector floor).
// ---------------------------------------------------------------------------
__global__ void fill_kernel(const void* __restrict__ edge_index,
                            const float* __restrict__ edge_weight) {
    int e = blockIdx.x * blockDim.x + threadIdx.x;
    if (e >= N_EDGES) return;
    long long dst, src;
    if (g_is64) {
        const long long* p = (const long long*)edge_index;
        dst = __ldcs(p + e);
        src = __ldcs(p + N_EDGES + e);
    } else {
        const int* p = (const int*)edge_index;
        dst = __ldcs(p + e);
        src = __ldcs(p + N_EDGES + e);
    }
    if ((unsigned long long)dst >= N_NODES ||
        (unsigned long long)src >= N_NODES) return;
    float w = __ldcs(edge_weight + e);
    int pos = atomicAdd(&g_cnt[(int)dst], 1);
    if (pos < BCAP) {
        unsigned long long pk =
            ((unsigned long long)__float_as_uint(w) << 32) | (unsigned int)src;
        g_buckets[(size_t)dst * BCAP + pos] = pk;
    }
}

// ---------------------------------------------------------------------------
// 2) gather: one warp per node (measured-best loop structure, unchanged);
//    output stored as fp16 (uint2).
// ---------------------------------------------------------------------------
__global__ void __launch_bounds__(256)
gather_kernel(const float* __restrict__ ego) {
    int gid  = blockIdx.x * blockDim.x + threadIdx.x;
    int lane = gid & 31;
    int node = gid >> 5;
    if (node >= N_NODES) return;

    int deg = min(g_cnt[node], BCAP);
    const unsigned long long* bucket = g_buckets + (size_t)node * BCAP;

    float4 a = *reinterpret_cast<const float4*>(ego + (size_t)node * D + lane * 4);

    int e = 0;
    while (e + 32 <= deg) {
        unsigned long long pk = __ldcs(bucket + e + lane);
#pragma unroll
        for (int j0 = 0; j0 < 32; j0 += 4) {
            uint2 h[4];
            float w[4];
#pragma unroll
            for (int jj = 0; jj < 4; jj++) {
                unsigned long long p = __shfl_sync(0xffffffffu, pk, j0 + jj);
                int src = (int)(p & 0xffffffffu);
                w[jj]   = __uint_as_float((unsigned)(p >> 32));
                h[jj]   = *reinterpret_cast<const uint2*>(
                              g_ego16 + (size_t)src * D + lane * 4);
            }
#pragma unroll
            for (int jj = 0; jj < 4; jj++) {
                float2 f01 = __half22float2(bits_h2(h[jj].x));
                float2 f23 = __half22float2(bits_h2(h[jj].y));
                a.x = fmaf(w[jj], f01.x, a.x);
                a.y = fmaf(w[jj], f01.y, a.y);
                a.z = fmaf(w[jj], f23.x, a.z);
                a.w = fmaf(w[jj], f23.y, a.w);
            }
        }
        e += 32;
    }
    int n = deg - e;
    if (n > 0) {
        unsigned long long pk = (lane < n) ? __ldcs(bucket + e + lane) : 0ull;
        for (int j = 0; j < n; j++) {
            unsigned long long p = __shfl_sync(0xffffffffu, pk, j);
            int src = (int)(p & 0xffffffffu);
            float w = __uint_as_float((unsigned)(p >> 32));
            uint2 h = *reinterpret_cast<const uint2*>(
                          g_ego16 + (size_t)src * D + lane * 4);
            float2 f01 = __half22float2(bits_h2(h.x));
            float2 f23 = __half22float2(bits_h2(h.y));
            a.x = fmaf(w, f01.x, a.x);
            a.y = fmaf(w, f01.y, a.y);
            a.z = fmaf(w, f23.x, a.z);
            a.w = fmaf(w, f23.y, a.w);
        }
    }
    uint2 o;
    o.x = h2_bits(__floats2half2_rn(a.x, a.y));
    o.y = h2_bits(__floats2half2_rn(a.z, a.w));
    *reinterpret_cast<uint2*>(g_x16 + (size_t)node * D + lane * 4) = o;
}

// ---------------------------------------------------------------------------
// 3) GEMM: out = leaky_relu(X @ W^T + b), fp16 mma.sync.m16n8k16, f32 accum.
//    Whole X/W tiles in smem; fragments loaded via ldmatrix (LDSM):
//    6 LDSM per k-step instead of 24 scalar LDS.
// ---------------------------------------------------------------------------
#define GBM 128
#define XW_STRIDE 136     // halves per row; 272B row stride -> LDSM conflict-free
#define GEMM_SMEM_BYTES (2 * 128 * XW_STRIDE * 2)       // 69632 B

__device__ __forceinline__ void mma_f16(float d[4], const uint32_t a[4],
                                        const uint32_t b[2]) {
    asm volatile(
        "mma.sync.aligned.m16n8k16.row.col.f32.f16.f16.f32 "
        "{%0,%1,%2,%3}, {%4,%5,%6,%7}, {%8,%9}, {%0,%1,%2,%3};"
        : "+f"(d[0]), "+f"(d[1]), "+f"(d[2]), "+f"(d[3])
        : "r"(a[0]), "r"(a[1]), "r"(a[2]), "r"(a[3]),
          "r"(b[0]), "r"(b[1]));
}

__device__ __forceinline__ void ldsm_x4(uint32_t r[4], const __half* p) {
    uint32_t addr = (uint32_t)__cvta_generic_to_shared(p);
    asm volatile(
        "ldmatrix.sync.aligned.m8n8.x4.shared.b16 {%0, %1, %2, %3}, [%4];"
        : "=r"(r[0]), "=r"(r[1]), "=r"(r[2]), "=r"(r[3])
        : "r"(addr));
}

__global__ void __launch_bounds__(256, 2)
gemm_kernel(const float* __restrict__ W,
            const float* __restrict__ bias,
            float* __restrict__ out) {
    extern __shared__ __half smem_h[];
    __half* Xs  = smem_h;                    // [r][k] fp16, stride 136
    __half* Wsm = smem_h + 128 * XW_STRIDE;  // [j][k] fp16, stride 136

    const int tid  = threadIdx.x;
    const int warp = tid >> 5;
    const int lane = tid & 31;
    const int g    = lane >> 2;
    const int t    = lane & 3;
    const int wm   = (warp >> 1) * 32;   // 0,32,64,96
    const int wn   = (warp & 1) * 64;    // 0,64
    const int block_row = blockIdx.x * GBM;

    // ldmatrix per-lane source rows/cols (within a 16x16 A tile / 16x16 B pair)
    const int a_row = lane & 15;            // 0..15
    const int a_koff = (lane >> 4) * 8;     // 0 or 8
    const int b_row = ((lane & 16) >> 1) + (lane & 7);   // 0..15 (8..15 for hi lanes)
    const int b_koff = ((lane >> 3) & 1) * 8;            // 0 or 8

    // load whole X tile (128x128 fp16): 8 uint4 per thread
#pragma unroll
    for (int it = 0; it < 8; it++) {
        int i  = tid + it * 256;         // 0..2047
        int r  = i >> 4;                 // 0..127
        int c8 = i & 15;                 // 0..15 (8 halves each)
        int row = block_row + r;
        uint4 v = make_uint4(0u, 0u, 0u, 0u);
        if (row < N_NODES)
            v = *reinterpret_cast<const uint4*>(g_x16 + (size_t)row * D + c8 * 8);
        *reinterpret_cast<uint4*>(Xs + r * XW_STRIDE + c8 * 8) = v;
    }
    // load whole W tile, f32 -> fp16: 8 x (2 float4 -> uint4) per thread
#pragma unroll
    for (int it = 0; it < 8; it++) {
        int i  = tid + it * 256;         // 0..2047
        int j  = i >> 4;                 // 0..127
        int c8 = i & 15;                 // 0..15
        float4 v0 = *reinterpret_cast<const float4*>(W + j * D + c8 * 8);
        float4 v1 = *reinterpret_cast<const float4*>(W + j * D + c8 * 8 + 4);
        uint4 o;
        o.x = h2_bits(__floats2half2_rn(v0.x, v0.y));
        o.y = h2_bits(__floats2half2_rn(v0.z, v0.w));
        o.z = h2_bits(__floats2half2_rn(v1.x, v1.y));
        o.w = h2_bits(__floats2half2_rn(v1.z, v1.w));
        *reinterpret_cast<uint4*>(Wsm + j * XW_STRIDE + c8 * 8) = o;
    }
    __syncthreads();

    float acc[2][8][4];
#pragma unroll
    for (int mt = 0; mt < 2; mt++)
#pragma unroll
        for (int nt = 0; nt < 8; nt++)
#pragma unroll
            for (int r = 0; r < 4; r++) acc[mt][nt][r] = 0.0f;

#pragma unroll
    for (int ksi = 0; ksi < 8; ksi++) {
        int ks = ksi * 16;
        // A fragments: one ldmatrix.x4 per 16-row subtile
        uint32_t afrag[2][4];
#pragma unroll
        for (int mt = 0; mt < 2; mt++) {
            const __half* pa = Xs + (wm + mt * 16 + a_row) * XW_STRIDE
                                  + ks + a_koff;
            ldsm_x4(afrag[mt], pa);
        }
        // B fragments: one ldmatrix.x4 covers two nt (16 output cols)
#pragma unroll
        for (int nt2 = 0; nt2 < 4; nt2++) {
            uint32_t b4[4];
            const __half* pb = Wsm + (wn + nt2 * 16 + b_row) * XW_STRIDE
                                   + ks + b_koff;
            ldsm_x4(b4, pb);
            mma_f16(acc[0][nt2 * 2    ], afrag[0], b4);      // b4[0],b4[1]
            mma_f16(acc[1][nt2 * 2    ], afrag[1], b4);
            mma_f16(acc[0][nt2 * 2 + 1], afrag[0], b4 + 2);  // b4[2],b4[3]
            mma_f16(acc[1][nt2 * 2 + 1], afrag[1], b4 + 2);
        }
    }

    // epilogue: + bias, leaky relu, store
#pragma unroll
    for (int mt = 0; mt < 2; mt++) {
        int row0 = block_row + wm + mt * 16 + g;
#pragma unroll
        for (int nt = 0; nt < 8; nt++) {
            int col = wn + nt * 8 + t * 2;
            float2 bv = *reinterpret_cast<const float2*>(bias + col);
            float2 o;
            if (row0 < N_NODES) {
                o.x = acc[mt][nt][0] + bv.x;
                o.y = acc[mt][nt][1] + bv.y;
                o.x = o.x > 0.f ? o.x : 0.01f * o.x;
                o.y = o.y > 0.f ? o.y : 0.01f * o.y;
                *reinterpret_cast<float2*>(out + (size_t)row0 * D + col) = o;
            }
            int row1 = row0 + 8;
            if (row1 < N_NODES) {
                o.x = acc[mt][nt][2] + bv.x;
                o.y = acc[mt][nt][3] + bv.y;
                o.x = o.x > 0.f ? o.x : 0.01f * o.x;
                o.y = o.y > 0.f ? o.y : 0.01f * o.y;
                *reinterpret_cast<float2*>(out + (size_t)row1 * D + col) = o;
            }
        }
    }
}

// ---------------------------------------------------------------------------
extern "C" void kernel_launch(void* const* d_in, const int* in_sizes, int n_in,
                              void* d_out, int out_size) {
    const float* ego = (const float*)d_in[0];
    const void*  ei  = d_in[1];
    const float* ew  = (const float*)d_in[2];
    const float* W   = (const float*)d_in[3];
    const float* b   = (const float*)d_in[4];
    float* out = (float*)d_out;

    cudaFuncSetAttribute(gemm_kernel,
                         cudaFuncAttributeMaxDynamicSharedMemorySize,
                         GEMM_SMEM_BYTES);

    // 0) fused detect + zero + fp16 convert
    {
        int n8 = N_NODES * D / 8;
        prep_kernel<<<(n8 + 255) / 256, 256>>>(ego, (const long long*)ei);
    }
    // 1) bucket fill
    {
        int blocks = (N_EDGES + 255) / 256;
        fill_kernel<<<blocks, 256>>>(ei, ew);
    }
    // 2) gather
    {
        long long total = (long long)N_NODES * 32;
        int blocks = (int)((total + 255) / 256);
        gather_kernel<<<blocks, 256>>>(ego);
    }
    // 3) GEMM + bias + leaky relu (fp16 tensor cores + ldmatrix)
    {
        int blocks = (N_NODES + GBM - 1) / GBM;
        gemm_kernel<<<blocks, 256, GEMM_SMEM_BYTES>>>(W, b, out);
    }
}

// round 17
// speedup vs baseline: 1.0551x; 1.0551x over previous
#include <cuda_runtime.h>
#include <cuda_bf16.h>
#include <cuda_fp16.h>
#include <cstdint>

#define N_NODES 100000
#define N_EDGES 1600000
#define D 128
#define BCAP 64          // bucket capacity; P(deg>=64)~1e-20 for Poisson(16)

// Scratch (static __device__ per allocation rules)
__device__ __half g_x16[N_NODES * D];                   // fp16 (ego+side) for GEMM
__device__ __half g_ego16[N_NODES * D];                 // fp16 mirror of ego
__device__ __half g_w16[D * D];                         // fp16 mirror of W
__device__ int    g_cnt[N_NODES];                       // per-dst cursor/degree
__device__ unsigned long long g_buckets[(size_t)N_NODES * BCAP];
__device__ int    g_is64;

__device__ __forceinline__ uint32_t h2_bits(__half2 h) {
    return *reinterpret_cast<uint32_t*>(&h);
}
__device__ __forceinline__ __half2 bits_h2(uint32_t u) {
    return *reinterpret_cast<__half2*>(&u);
}

// ---------------------------------------------------------------------------
// 0) prep: fused detect + zero-cursors + fp16 converts (ego AND W).
// ---------------------------------------------------------------------------
__global__ void prep_kernel(const float* __restrict__ ego,
                            const long long* __restrict__ ei,
                            const float* __restrict__ W) {
    int i = blockIdx.x * blockDim.x + threadIdx.x;

    if (blockIdx.x == 0 && threadIdx.x < 32) {
        long long v = ei[threadIdx.x];
        unsigned bad = __ballot_sync(0xffffffffu,
                                     (unsigned long long)v >= (unsigned long long)N_NODES);
        if (threadIdx.x == 0) g_is64 = (bad == 0u);
    }

    if (i < N_NODES) g_cnt[i] = 0;

    // W -> fp16 mirror: 16384 elems / 8 per thread = 2048 threads
    if (i < D * D / 8) {
        float4 a = reinterpret_cast<const float4*>(W)[2 * i];
        float4 b = reinterpret_cast<const float4*>(W)[2 * i + 1];
        uint4 o;
        o.x = h2_bits(__floats2half2_rn(a.x, a.y));
        o.y = h2_bits(__floats2half2_rn(a.z, a.w));
        o.z = h2_bits(__floats2half2_rn(b.x, b.y));
        o.w = h2_bits(__floats2half2_rn(b.z, b.w));
        reinterpret_cast<uint4*>(g_w16)[i] = o;
    }

    const int n8 = N_NODES * D / 8;
    if (i < n8) {
        float4 a = reinterpret_cast<const float4*>(ego)[2 * i];
        float4 b = reinterpret_cast<const float4*>(ego)[2 * i + 1];
        uint4 o;
        o.x = h2_bits(__floats2half2_rn(a.x, a.y));
        o.y = h2_bits(__floats2half2_rn(a.z, a.w));
        o.z = h2_bits(__floats2half2_rn(b.x, b.y));
        o.w = h2_bits(__floats2half2_rn(b.z, b.w));
        reinterpret_cast<uint4*>(g_ego16)[i] = o;
    }
}

// ---------------------------------------------------------------------------
// 1) fill: direct bucketing (measured-best scalar form; ~L2-sector floor).
// ---------------------------------------------------------------------------
__global__ void fill_kernel(const void* __restrict__ edge_index,
                            const float* __restrict__ edge_weight) {
    int e = blockIdx.x * blockDim.x + threadIdx.x;
    if (e >= N_EDGES) return;
    long long dst, src;
    if (g_is64) {
        const long long* p = (const long long*)edge_index;
        dst = __ldcs(p + e);
        src = __ldcs(p + N_EDGES + e);
    } else {
        const int* p = (const int*)edge_index;
        dst = __ldcs(p + e);
        src = __ldcs(p + N_EDGES + e);
    }
    if ((unsigned long long)dst >= N_NODES ||
        (unsigned long long)src >= N_NODES) return;
    float w = __ldcs(edge_weight + e);
    int pos = atomicAdd(&g_cnt[(int)dst], 1);
    if (pos < BCAP) {
        unsigned long long pk =
            ((unsigned long long)__float_as_uint(w) << 32) | (unsigned int)src;
        g_buckets[(size_t)dst * BCAP + pos] = pk;
    }
}

// ---------------------------------------------------------------------------
// 2) gather: one warp per node (measured-best loop structure, unchanged);
//    output stored as fp16 (uint2).
// ---------------------------------------------------------------------------
__global__ void __launch_bounds__(256)
gather_kernel(const float* __restrict__ ego) {
    int gid  = blockIdx.x * blockDim.x + threadIdx.x;
    int lane = gid & 31;
    int node = gid >> 5;
    if (node >= N_NODES) return;

    int deg = min(g_cnt[node], BCAP);
    const unsigned long long* bucket = g_buckets + (size_t)node * BCAP;

    float4 a = *reinterpret_cast<const float4*>(ego + (size_t)node * D + lane * 4);

    int e = 0;
    while (e + 32 <= deg) {
        unsigned long long pk = __ldcs(bucket + e + lane);
#pragma unroll
        for (int j0 = 0; j0 < 32; j0 += 4) {
            uint2 h[4];
            float w[4];
#pragma unroll
            for (int jj = 0; jj < 4; jj++) {
                unsigned long long p = __shfl_sync(0xffffffffu, pk, j0 + jj);
                int src = (int)(p & 0xffffffffu);
                w[jj]   = __uint_as_float((unsigned)(p >> 32));
                h[jj]   = *reinterpret_cast<const uint2*>(
                              g_ego16 + (size_t)src * D + lane * 4);
            }
#pragma unroll
            for (int jj = 0; jj < 4; jj++) {
                float2 f01 = __half22float2(bits_h2(h[jj].x));
                float2 f23 = __half22float2(bits_h2(h[jj].y));
                a.x = fmaf(w[jj], f01.x, a.x);
                a.y = fmaf(w[jj], f01.y, a.y);
                a.z = fmaf(w[jj], f23.x, a.z);
                a.w = fmaf(w[jj], f23.y, a.w);
            }
        }
        e += 32;
    }
    int n = deg - e;
    if (n > 0) {
        unsigned long long pk = (lane < n) ? __ldcs(bucket + e + lane) : 0ull;
        for (int j = 0; j < n; j++) {
            unsigned long long p = __shfl_sync(0xffffffffu, pk, j);
            int src = (int)(p & 0xffffffffu);
            float w = __uint_as_float((unsigned)(p >> 32));
            uint2 h = *reinterpret_cast<const uint2*>(
                          g_ego16 + (size_t)src * D + lane * 4);
            float2 f01 = __half22float2(bits_h2(h.x));
            float2 f23 = __half22float2(bits_h2(h.y));
            a.x = fmaf(w, f01.x, a.x);
            a.y = fmaf(w, f01.y, a.y);
            a.z = fmaf(w, f23.x, a.z);
            a.w = fmaf(w, f23.y, a.w);
        }
    }
    uint2 o;
    o.x = h2_bits(__floats2half2_rn(a.x, a.y));
    o.y = h2_bits(__floats2half2_rn(a.z, a.w));
    *reinterpret_cast<uint2*>(g_x16 + (size_t)node * D + lane * 4) = o;
}

// ---------------------------------------------------------------------------
// 3) GEMM: out = leaky_relu(X @ W^T + b), fp16 mma.sync.m16n8k16, f32 accum.
//    R15 measured-best structure (scalar-LDS fragments); W now loaded from
//    the precomputed fp16 mirror (half the bytes, no cvt in prologue).
// ---------------------------------------------------------------------------
#define GBM 128
#define XW_STRIDE 136     // halves per row (stride 68 words -> conflict-free)
#define GEMM_SMEM_BYTES (2 * 128 * XW_STRIDE * 2)       // 69632 B

__device__ __forceinline__ void mma_f16(float d[4], const uint32_t a[4],
                                        const uint32_t b[2]) {
    asm volatile(
        "mma.sync.aligned.m16n8k16.row.col.f32.f16.f16.f32 "
        "{%0,%1,%2,%3}, {%4,%5,%6,%7}, {%8,%9}, {%0,%1,%2,%3};"
        : "+f"(d[0]), "+f"(d[1]), "+f"(d[2]), "+f"(d[3])
        : "r"(a[0]), "r"(a[1]), "r"(a[2]), "r"(a[3]),
          "r"(b[0]), "r"(b[1]));
}

__global__ void __launch_bounds__(256, 2)
gemm_kernel(const float* __restrict__ bias,
            float* __restrict__ out) {
    extern __shared__ __half smem_h[];
    __half* Xs  = smem_h;                    // [r][k] fp16, stride 136
    __half* Wsm = smem_h + 128 * XW_STRIDE;  // [j][k] fp16, stride 136

    const int tid  = threadIdx.x;
    const int warp = tid >> 5;
    const int lane = tid & 31;
    const int g    = lane >> 2;
    const int t    = lane & 3;
    const int wm   = (warp >> 1) * 32;   // 0,32,64,96
    const int wn   = (warp & 1) * 64;    // 0,64
    const int block_row = blockIdx.x * GBM;

    // load whole X tile (128x128 fp16): 8 uint4 per thread
#pragma unroll
    for (int it = 0; it < 8; it++) {
        int i  = tid + it * 256;         // 0..2047
        int r  = i >> 4;                 // 0..127
        int c8 = i & 15;                 // 0..15 (8 halves each)
        int row = block_row + r;
        uint4 v = make_uint4(0u, 0u, 0u, 0u);
        if (row < N_NODES)
            v = *reinterpret_cast<const uint4*>(g_x16 + (size_t)row * D + c8 * 8);
        *reinterpret_cast<uint4*>(Xs + r * XW_STRIDE + c8 * 8) = v;
    }
    // load whole W tile from fp16 mirror: 8 uint4 per thread
#pragma unroll
    for (int it = 0; it < 8; it++) {
        int i  = tid + it * 256;         // 0..2047
        int j  = i >> 4;                 // 0..127
        int c8 = i & 15;                 // 0..15
        uint4 v = *reinterpret_cast<const uint4*>(g_w16 + j * D + c8 * 8);
        *reinterpret_cast<uint4*>(Wsm + j * XW_STRIDE + c8 * 8) = v;
    }
    __syncthreads();

    float acc[2][8][4];
#pragma unroll
    for (int mt = 0; mt < 2; mt++)
#pragma unroll
        for (int nt = 0; nt < 8; nt++)
#pragma unroll
            for (int r = 0; r < 4; r++) acc[mt][nt][r] = 0.0f;

#pragma unroll
    for (int ksi = 0; ksi < 8; ksi++) {
        int ks = ksi * 16;
        uint32_t afrag[2][4];
#pragma unroll
        for (int mt = 0; mt < 2; mt++) {
            int rbase = wm + mt * 16;
            afrag[mt][0] = *reinterpret_cast<const uint32_t*>(
                Xs + (rbase + g    ) * XW_STRIDE + ks + t * 2);
            afrag[mt][1] = *reinterpret_cast<const uint32_t*>(
                Xs + (rbase + g + 8) * XW_STRIDE + ks + t * 2);
            afrag[mt][2] = *reinterpret_cast<const uint32_t*>(
                Xs + (rbase + g    ) * XW_STRIDE + ks + 8 + t * 2);
            afrag[mt][3] = *reinterpret_cast<const uint32_t*>(
                Xs + (rbase + g + 8) * XW_STRIDE + ks + 8 + t * 2);
        }
#pragma unroll
        for (int nt = 0; nt < 8; nt++) {
            int nb = wn + nt * 8 + g;
            uint32_t bfrag[2];
            bfrag[0] = *reinterpret_cast<const uint32_t*>(
                Wsm + nb * XW_STRIDE + ks + t * 2);
            bfrag[1] = *reinterpret_cast<const uint32_t*>(
                Wsm + nb * XW_STRIDE + ks + 8 + t * 2);
            mma_f16(acc[0][nt], afrag[0], bfrag);
            mma_f16(acc[1][nt], afrag[1], bfrag);
        }
    }

    // epilogue: + bias, leaky relu, store
#pragma unroll
    for (int mt = 0; mt < 2; mt++) {
        int row0 = block_row + wm + mt * 16 + g;
#pragma unroll
        for (int nt = 0; nt < 8; nt++) {
            int col = wn + nt * 8 + t * 2;
            float2 bv = *reinterpret_cast<const float2*>(bias + col);
            float2 o;
            if (row0 < N_NODES) {
                o.x = acc[mt][nt][0] + bv.x;
                o.y = acc[mt][nt][1] + bv.y;
                o.x = o.x > 0.f ? o.x : 0.01f * o.x;
                o.y = o.y > 0.f ? o.y : 0.01f * o.y;
                *reinterpret_cast<float2*>(out + (size_t)row0 * D + col) = o;
            }
            int row1 = row0 + 8;
            if (row1 < N_NODES) {
                o.x = acc[mt][nt][2] + bv.x;
                o.y = acc[mt][nt][3] + bv.y;
                o.x = o.x > 0.f ? o.x : 0.01f * o.x;
                o.y = o.y > 0.f ? o.y : 0.01f * o.y;
                *reinterpret_cast<float2*>(out + (size_t)row1 * D + col) = o;
            }
        }
    }
}

// ---------------------------------------------------------------------------
extern "C" void kernel_launch(void* const* d_in, const int* in_sizes, int n_in,
                              void* d_out, int out_size) {
    const float* ego = (const float*)d_in[0];
    const void*  ei  = d_in[1];
    const float* ew  = (const float*)d_in[2];
    const float* W   = (const float*)d_in[3];
    const float* b   = (const float*)d_in[4];
    float* out = (float*)d_out;

    cudaFuncSetAttribute(gemm_kernel,
                         cudaFuncAttributeMaxDynamicSharedMemorySize,
                         GEMM_SMEM_BYTES);

    // 0) fused detect + zero + fp16 converts (ego + W)
    {
        int n8 = N_NODES * D / 8;
        prep_kernel<<<(n8 + 255) / 256, 256>>>(ego, (const long long*)ei, W);
    }
    // 1) bucket fill
    {
        int blocks = (N_EDGES + 255) / 256;
        fill_kernel<<<blocks, 256>>>(ei, ew);
    }
    // 2) gather
    {
        long long total = (long long)N_NODES * 32;
        int blocks = (int)((total + 255) / 256);
        gather_kernel<<<blocks, 256>>>(ego);
    }
    // 3) GEMM + bias + leaky relu (fp16 tensor cores, precomputed W16)
    {
        int blocks = (N_NODES + GBM - 1) / GBM;
        gemm_kernel<<<blocks, 256, GEMM_SMEM_BYTES>>>(b, out);
    }
}